// round 7
// baseline (speedup 1.0000x reference)
#include <cuda_runtime.h>
#include <cuda_bf16.h>
#include <math.h>
#include <stdint.h>

#define BATCH 4
#define T 4096
#define C 768
#define H 64
#define M_TOT (BATCH * T)
#define NSPLIT 4

// scale folded with log2(e): softmax computed in exp2 domain
#define SC_LOG2 0.180336881f   // 0.125 * log2(e)

// ---- pre-converted bf16 hi/lo operand arrays ----
__device__ __align__(16) __nv_bfloat16 g_xhi[(size_t)M_TOT * C];
__device__ __align__(16) __nv_bfloat16 g_xlo[(size_t)M_TOT * C];
__device__ __align__(16) __nv_bfloat16 g_Whi[3 * C * H];
__device__ __align__(16) __nv_bfloat16 g_Wlo[3 * C * H];
__device__ __align__(16) __nv_bfloat16 g_Qhi[M_TOT * H];
__device__ __align__(16) __nv_bfloat16 g_Qlo[M_TOT * H];
__device__ __align__(16) __nv_bfloat16 g_Khi[M_TOT * H];
__device__ __align__(16) __nv_bfloat16 g_Klo[M_TOT * H];
__device__ __align__(16) __nv_bfloat16 g_Vhi[M_TOT * H];
__device__ __align__(16) __nv_bfloat16 g_Vlo[M_TOT * H];
__device__ float g_m[M_TOT * NSPLIT];
__device__ float g_l[M_TOT * NSPLIT];
__device__ float g_acc[(size_t)M_TOT * NSPLIT * H];

// ============================================================================
// Primitives
// ============================================================================
__device__ __forceinline__ uint32_t smem_to_u32(const void* smem_ptr) {
    uint32_t addr;
    asm("{ .reg .u64 tmp; cvta.to.shared.u64 tmp, %1; cvt.u32.u64 %0, tmp; }"
        : "=r"(addr) : "l"(smem_ptr));
    return addr;
}

__device__ __forceinline__ void mma16816(float* d, const uint32_t* a, const uint32_t* b) {
    asm volatile(
        "mma.sync.aligned.m16n8k16.row.col.f32.bf16.bf16.f32 "
        "{%0,%1,%2,%3}, {%4,%5,%6,%7}, {%8,%9}, {%0,%1,%2,%3};"
        : "+f"(d[0]), "+f"(d[1]), "+f"(d[2]), "+f"(d[3])
        : "r"(a[0]), "r"(a[1]), "r"(a[2]), "r"(a[3]), "r"(b[0]), "r"(b[1]));
}

__device__ __forceinline__ void ldsm_x4(uint32_t* r, uint32_t a) {
    asm volatile("ldmatrix.sync.aligned.m8n8.x4.shared.b16 {%0,%1,%2,%3}, [%4];"
        : "=r"(r[0]), "=r"(r[1]), "=r"(r[2]), "=r"(r[3]) : "r"(a));
}

__device__ __forceinline__ void ldsm_x4_t(uint32_t* r, uint32_t a) {
    asm volatile("ldmatrix.sync.aligned.m8n8.x4.trans.shared.b16 {%0,%1,%2,%3}, [%4];"
        : "=r"(r[0]), "=r"(r[1]), "=r"(r[2]), "=r"(r[3]) : "r"(a));
}

#define CP16(dst, src) \
    asm volatile("cp.async.cg.shared.global [%0], [%1], 16;" \
                 :: "r"(dst), "l"(src) : "memory")
#define CP_COMMIT() asm volatile("cp.async.commit_group;" ::: "memory")
#define CP_WAIT0()  asm volatile("cp.async.wait_group 0;" ::: "memory")
#define CP_WAIT1()  asm volatile("cp.async.wait_group 1;" ::: "memory")
#define CP_WAIT2()  asm volatile("cp.async.wait_group 2;" ::: "memory")

__device__ __forceinline__ void cvt_hilo(float vx, float vy, uint32_t& hi, uint32_t& lo) {
    __nv_bfloat162 h = __floats2bfloat162_rn(vx, vy);
    hi = *reinterpret_cast<uint32_t*>(&h);
    float rx = vx - __bfloat162float(h.x);
    float ry = vy - __bfloat162float(h.y);
    __nv_bfloat162 l2 = __floats2bfloat162_rn(rx, ry);
    lo = *reinterpret_cast<uint32_t*>(&l2);
}

// SMEM tile: 64 rows x 64 bf16, 144B row stride
#define SKB 144
#define TILE_BYTES (64 * SKB)        // 9216 (one of hi or lo)
#define SLOT_BYTES (2 * TILE_BYTES)  // 18432 (hi + lo)

// ---------------------------------------------------------------------------
// Prep kernels
// ---------------------------------------------------------------------------
__global__ __launch_bounds__(256) void prep_x_kernel(const float* __restrict__ x)
{
    size_t i = ((size_t)blockIdx.x * 256 + threadIdx.x) * 8;
    float4 a = *(const float4*)(x + i);
    float4 b = *(const float4*)(x + i + 4);
    uint32_t h[4], l[4];
    cvt_hilo(a.x, a.y, h[0], l[0]);
    cvt_hilo(a.z, a.w, h[1], l[1]);
    cvt_hilo(b.x, b.y, h[2], l[2]);
    cvt_hilo(b.z, b.w, h[3], l[3]);
    *(uint4*)(g_xhi + i) = make_uint4(h[0], h[1], h[2], h[3]);
    *(uint4*)(g_xlo + i) = make_uint4(l[0], l[1], l[2], l[3]);
}

__global__ __launch_bounds__(256) void prep_w_kernel(
    const float* __restrict__ Wq, const float* __restrict__ Wk,
    const float* __restrict__ Wv)
{
    size_t i = ((size_t)blockIdx.x * 256 + threadIdx.x) * 8;
    int which = (int)(i / (C * H));
    const float* W = (which == 0) ? Wq : (which == 1) ? Wk : Wv;
    size_t local = i - (size_t)which * (C * H);
    float4 a = *(const float4*)(W + local);
    float4 b = *(const float4*)(W + local + 4);
    uint32_t h[4], l[4];
    cvt_hilo(a.x, a.y, h[0], l[0]);
    cvt_hilo(a.z, a.w, h[1], l[1]);
    cvt_hilo(b.x, b.y, h[2], l[2]);
    cvt_hilo(b.z, b.w, h[3], l[3]);
    *(uint4*)(g_Whi + i) = make_uint4(h[0], h[1], h[2], h[3]);
    *(uint4*)(g_Wlo + i) = make_uint4(l[0], l[1], l[2], l[3]);
}

extern __shared__ __align__(16) char dyn_sm[];

// ---------------------------------------------------------------------------
// Kernel 1: QKV projection, 2-stage pipelined.
// ---------------------------------------------------------------------------
__global__ __launch_bounds__(128, 3) void qkv_mma_kernel()
{
    const int y    = blockIdx.y;
    const int tid  = threadIdx.x;
    const int wid  = tid >> 5;
    const int lane = tid & 31;
    const int m0g  = blockIdx.x * 64;
    const uint32_t smb = smem_to_u32(dyn_sm);

    const char* srcs[4] = {
        (const char*)g_xhi, (const char*)g_xlo,
        (const char*)(g_Whi + (size_t)y * C * H),
        (const char*)(g_Wlo + (size_t)y * C * H) };

    auto stage = [&](int t) {
        uint32_t base = smb + (t & 1) * (4 * TILE_BYTES);
        int k0 = t * 64;
#pragma unroll
        for (int i = 0; i < 16; i++) {
            int id = i * 128 + tid;
            const int arr = i >> 2;
            int within = id & 511;
            int r = within >> 3, c = within & 7;
            uint32_t dst = base + arr * TILE_BYTES + r * SKB + c * 16;
            const char* src = (arr < 2)
                ? srcs[arr] + ((size_t)(m0g + r) * C + k0 + c * 8) * 2
                : srcs[arr] + ((size_t)(k0 + r) * H + c * 8) * 2;
            CP16(dst, src);
        }
        CP_COMMIT();
    };

    float o[8][4];
#pragma unroll
    for (int nt = 0; nt < 8; nt++)
#pragma unroll
        for (int e = 0; e < 4; e++) o[nt][e] = 0.0f;

    const int a_row  = wid * 16 + (lane & 7) + ((lane >> 3) & 1) * 8;
    const int a_colb = (lane >> 4) * 8;
    const int g      = lane >> 3;
    const int t_row  = (lane & 7) + (g & 1) * 8;
    const int t_colb = (g >> 1) * 8;

    const int NT = C / 64;
    stage(0);
    stage(1);

    for (int t = 0; t < NT; t++) {
        if (t + 2 <= NT) CP_WAIT1(); else CP_WAIT0();
        __syncthreads();
        uint32_t bb = smb + (t & 1) * (4 * TILE_BYTES);

        uint32_t axh[4][4], axl[4][4];
#pragma unroll
        for (int k = 0; k < 4; k++) {
            uint32_t ad = a_row * SKB + (k * 16 + a_colb) * 2;
            ldsm_x4(axh[k], bb + 0          + ad);
            ldsm_x4(axl[k], bb + TILE_BYTES + ad);
        }

#pragma unroll
        for (int np = 0; np < 4; np++) {
#pragma unroll
            for (int k = 0; k < 4; k++) {
                uint32_t bh[4], bl[4];
                uint32_t ad = (k * 16 + t_row) * SKB + (np * 16 + t_colb) * 2;
                ldsm_x4_t(bh, bb + 2 * TILE_BYTES + ad);
                ldsm_x4_t(bl, bb + 3 * TILE_BYTES + ad);
                mma16816(o[2 * np],     axh[k], bh);
                mma16816(o[2 * np + 1], axh[k], bh + 2);
                mma16816(o[2 * np],     axh[k], bl);
                mma16816(o[2 * np + 1], axh[k], bl + 2);
                mma16816(o[2 * np],     axl[k], bh);
                mma16816(o[2 * np + 1], axl[k], bh + 2);
            }
        }
        __syncthreads();
        if (t + 2 < NT) stage(t + 2);
    }

    __nv_bfloat16* ohi = (y == 0) ? g_Qhi : (y == 1) ? g_Khi : g_Vhi;
    __nv_bfloat16* olo = (y == 0) ? g_Qlo : (y == 1) ? g_Klo : g_Vlo;
    const int r0 = m0g + wid * 16 + (lane >> 2);
#pragma unroll
    for (int nt = 0; nt < 8; nt++) {
        int c = nt * 8 + (lane & 3) * 2;
        uint32_t hi, lo;
        cvt_hilo(o[nt][0], o[nt][1], hi, lo);
        *(uint32_t*)(ohi + (size_t)r0 * H + c) = hi;
        *(uint32_t*)(olo + (size_t)r0 * H + c) = lo;
        cvt_hilo(o[nt][2], o[nt][3], hi, lo);
        *(uint32_t*)(ohi + (size_t)(r0 + 8) * H + c) = hi;
        *(uint32_t*)(olo + (size_t)(r0 + 8) * H + c) = lo;
    }
}

// ---------------------------------------------------------------------------
// Kernel 2: flash attention, S(t+1)-over-softmax(t) overlap.
// grid = (T/64, NSPLIT, BATCH), block = 128 (4 warps x 16 queries).
// SMEM: K slot0 | K slot1 | V slot0 | V slot1  (each 18432 = hi+lo)
// ---------------------------------------------------------------------------
__global__ __launch_bounds__(128, 3) void flash_mma_kernel()
{
    const int b     = blockIdx.z;
    const int split = blockIdx.y;
    const int qt    = blockIdx.x;
    const int tid   = threadIdx.x;
    const int wid   = tid >> 5;
    const int lane  = tid & 31;
    const int q0    = qt * 64;

    const int seg_begin = split * (T / NSPLIT);
    const int seg_end   = min(seg_begin + T / NSPLIT, q0 + 64);

    if (seg_begin >= seg_end) {
        for (int r = tid; r < 64; r += 128) {
            size_t pb = ((size_t)(b * T) + q0 + r) * NSPLIT + split;
            g_m[pb] = -1e30f;
            g_l[pb] = 0.0f;
        }
        return;
    }

    const uint32_t smb = smem_to_u32(dyn_sm);
    const uint32_t kslot[2] = { smb,                  smb + SLOT_BYTES };
    const uint32_t vslot[2] = { smb + 2 * SLOT_BYTES, smb + 3 * SLOT_BYTES };

    const int NT = (seg_end - seg_begin + 63) / 64;

    auto stage_k = [&](int t) {
        uint32_t base = kslot[t & 1];
        int kt = seg_begin + t * 64;
#pragma unroll
        for (int i = 0; i < 8; i++) {
            int id = i * 128 + tid;
            const int arr = i >> 2;              // 0=hi 1=lo
            int within = id & 511;
            int r = within >> 3, c = within & 7;
            uint32_t dst = base + arr * TILE_BYTES + r * SKB + c * 16;
            const char* src = (const char*)(arr ? g_Klo : g_Khi)
                            + ((size_t)(b * T + kt + r) * H + c * 8) * 2;
            CP16(dst, src);
        }
    };
    auto stage_v = [&](int t) {
        uint32_t base = vslot[t & 1];
        int kt = seg_begin + t * 64;
#pragma unroll
        for (int i = 0; i < 8; i++) {
            int id = i * 128 + tid;
            const int arr = i >> 2;
            int within = id & 511;
            int r = within >> 3, c = within & 7;
            uint32_t dst = base + arr * TILE_BYTES + r * SKB + c * 16;
            const char* src = (const char*)(arr ? g_Vlo : g_Vhi)
                            + ((size_t)(b * T + kt + r) * H + c * 8) * 2;
            CP16(dst, src);
        }
    };

    // ---- Q fragments straight from global (canonical m16n8k16 A layout) ----
    uint32_t qh[4][4], ql[4][4];
    {
        const int rl = wid * 16 + (lane >> 2);
        const int tg = lane & 3;
        const uint32_t* Qh32 = (const uint32_t*)(g_Qhi + (size_t)(b * T + q0) * H);
        const uint32_t* Ql32 = (const uint32_t*)(g_Qlo + (size_t)(b * T + q0) * H);
#pragma unroll
        for (int k = 0; k < 4; k++) {
            int cb = k * 8 + tg;                 // u32 column (of 32 per row)
            qh[k][0] = Qh32[(size_t)rl * 32 + cb];
            qh[k][1] = Qh32[(size_t)(rl + 8) * 32 + cb];
            qh[k][2] = Qh32[(size_t)rl * 32 + cb + 4];
            qh[k][3] = Qh32[(size_t)(rl + 8) * 32 + cb + 4];
            ql[k][0] = Ql32[(size_t)rl * 32 + cb];
            ql[k][1] = Ql32[(size_t)(rl + 8) * 32 + cb];
            ql[k][2] = Ql32[(size_t)rl * 32 + cb + 4];
            ql[k][3] = Ql32[(size_t)(rl + 8) * 32 + cb + 4];
        }
    }

    // ---- prologue staging:  groups [K0V0][K1][V1] ----
    stage_k(0); stage_v(0); CP_COMMIT();
    if (NT > 1) { stage_k(1); CP_COMMIT(); stage_v(1); CP_COMMIT(); }
    if (NT > 1) CP_WAIT2(); else CP_WAIT0();
    __syncthreads();

    const int g      = lane >> 3;
    const int nt_row = (lane & 7) + (g >> 1) * 8;
    const int nt_colb = (g & 1) * 8;
    const int t_row  = (lane & 7) + (g & 1) * 8;
    const int t_colb = (g >> 1) * 8;

    // S-tile compute: s += 3-term Q * K(buf)^T
    auto computeS = [&](float (*s)[4], uint32_t kb) {
#pragma unroll
        for (int nt = 0; nt < 8; nt++)
#pragma unroll
            for (int e = 0; e < 4; e++) s[nt][e] = 0.0f;
#pragma unroll
        for (int np = 0; np < 4; np++) {
#pragma unroll
            for (int k = 0; k < 4; k++) {
                uint32_t bh[4], bl[4];
                uint32_t ad = (np * 16 + nt_row) * SKB + (k * 16 + nt_colb) * 2;
                ldsm_x4(bh, kb + ad);
                ldsm_x4(bl, kb + TILE_BYTES + ad);
                mma16816(s[2 * np],     qh[k], bh);
                mma16816(s[2 * np + 1], qh[k], bh + 2);
                mma16816(s[2 * np],     qh[k], bl);
                mma16816(s[2 * np + 1], qh[k], bl + 2);
                mma16816(s[2 * np],     ql[k], bh);
                mma16816(s[2 * np + 1], ql[k], bh + 2);
            }
        }
    };

    float o[8][4];
#pragma unroll
    for (int nt = 0; nt < 8; nt++)
#pragma unroll
        for (int e = 0; e < 4; e++) o[nt][e] = 0.0f;
    float m0 = -1e30f, m1 = -1e30f, l0 = 0.0f, l1 = 0.0f;

    const int row_i0 = (wid << 4) + (lane >> 2);

    float s_cur[8][4], s_nxt[8][4];
    computeS(s_cur, kslot[0]);
    // RACE FIX (R6 post-mortem): all warps must finish reading K0 from
    // kslot[0] before any warp's stage_k(2) below overwrites that slot.
    __syncthreads();

    for (int t = 0; t < NT; t++) {
        // top: stage K(t+2), wait so K(t+1) and V(t) are resident
        if (t + 2 < NT) { stage_k(t + 2); CP_COMMIT(); CP_WAIT2(); }
        else if (t + 1 < NT) CP_WAIT1();
        else CP_WAIT0();
        __syncthreads();

        // issue next tile's S MMAs first — they overlap with softmax below
        if (t + 1 < NT) computeS(s_nxt, kslot[(t + 1) & 1]);

        const int kt = seg_begin + t * 64;

        // ---- softmax(t) in exp2 domain ----
        const bool needmask = (kt + 63 > q0 + (wid << 4));
        float mn0 = -1e30f, mn1 = -1e30f;
#pragma unroll
        for (int nt = 0; nt < 8; nt++) {
#pragma unroll
            for (int e = 0; e < 4; e++) {
                float v = s_cur[nt][e] * SC_LOG2;
                if (needmask) {
                    int j = kt + nt * 8 + (lane & 3) * 2 + (e & 1);
                    int i = q0 + row_i0 + (e >> 1) * 8;
                    if (j > i) v = -INFINITY;
                }
                s_cur[nt][e] = v;
            }
            mn0 = fmaxf(mn0, fmaxf(s_cur[nt][0], s_cur[nt][1]));
            mn1 = fmaxf(mn1, fmaxf(s_cur[nt][2], s_cur[nt][3]));
        }
        mn0 = fmaxf(mn0, __shfl_xor_sync(0xFFFFFFFFu, mn0, 1));
        mn0 = fmaxf(mn0, __shfl_xor_sync(0xFFFFFFFFu, mn0, 2));
        mn1 = fmaxf(mn1, __shfl_xor_sync(0xFFFFFFFFu, mn1, 1));
        mn1 = fmaxf(mn1, __shfl_xor_sync(0xFFFFFFFFu, mn1, 2));
        mn0 = fmaxf(mn0, -1e30f);
        mn1 = fmaxf(mn1, -1e30f);

        float mnew0 = fmaxf(m0, mn0), mnew1 = fmaxf(m1, mn1);
        float a0 = exp2f(m0 - mnew0), a1 = exp2f(m1 - mnew1);
        m0 = mnew0; m1 = mnew1;

        float ls0 = 0.0f, ls1 = 0.0f;
#pragma unroll
        for (int nt = 0; nt < 8; nt++) {
            float p0 = exp2f(s_cur[nt][0] - mnew0);
            float p1 = exp2f(s_cur[nt][1] - mnew0);
            float p2 = exp2f(s_cur[nt][2] - mnew1);
            float p3 = exp2f(s_cur[nt][3] - mnew1);
            s_cur[nt][0] = p0; s_cur[nt][1] = p1;
            s_cur[nt][2] = p2; s_cur[nt][3] = p3;
            ls0 += p0 + p1;
            ls1 += p2 + p3;
            o[nt][0] *= a0; o[nt][1] *= a0;
            o[nt][2] *= a1; o[nt][3] *= a1;
        }
        ls0 += __shfl_xor_sync(0xFFFFFFFFu, ls0, 1);
        ls0 += __shfl_xor_sync(0xFFFFFFFFu, ls0, 2);
        ls1 += __shfl_xor_sync(0xFFFFFFFFu, ls1, 1);
        ls1 += __shfl_xor_sync(0xFFFFFFFFu, ls1, 2);
        l0 = l0 * a0 + ls0;
        l1 = l1 * a1 + ls1;

        // ---- O += P V(t) ----
        const uint32_t vb = vslot[t & 1];
#pragma unroll
        for (int k = 0; k < 4; k++) {
            uint32_t aPh[4], aPl[4];
#pragma unroll
            for (int h = 0; h < 2; h++) {
                int nt = 2 * k + h;
                cvt_hilo(s_cur[nt][0], s_cur[nt][1], aPh[h * 2 + 0], aPl[h * 2 + 0]);
                cvt_hilo(s_cur[nt][2], s_cur[nt][3], aPh[h * 2 + 1], aPl[h * 2 + 1]);
            }
#pragma unroll
            for (int dp = 0; dp < 4; dp++) {
                uint32_t bh[4], bl[4];
                uint32_t ad = (k * 16 + t_row) * SKB + (dp * 16 + t_colb) * 2;
                ldsm_x4_t(bh, vb + ad);
                ldsm_x4_t(bl, vb + TILE_BYTES + ad);
                mma16816(o[2 * dp],     aPh, bh);
                mma16816(o[2 * dp + 1], aPh, bh + 2);
                mma16816(o[2 * dp],     aPh, bl);
                mma16816(o[2 * dp + 1], aPh, bl + 2);
                mma16816(o[2 * dp],     aPl, bh);
                mma16816(o[2 * dp + 1], aPl, bh + 2);
            }
        }

        // bottom: after PV(t) consumed V(t), stage V(t+2) into that slot
        if (t + 2 < NT) {
            __syncthreads();
            stage_v(t + 2);
            CP_COMMIT();
        }

        // advance s
        if (t + 1 < NT) {
#pragma unroll
            for (int nt = 0; nt < 8; nt++)
#pragma unroll
                for (int e = 0; e < 4; e++) s_cur[nt][e] = s_nxt[nt][e];
        }
    }

    // ---- write split partials (m in log2 domain) ----
    const int r0g = q0 + row_i0;
    const size_t pb0 = ((size_t)(b * T) + r0g) * NSPLIT + split;
    const size_t pb1 = ((size_t)(b * T) + r0g + 8) * NSPLIT + split;
#pragma unroll
    for (int nt = 0; nt < 8; nt++) {
        int c = nt * 8 + (lane & 3) * 2;
        *(float2*)&g_acc[pb0 * H + c] = make_float2(o[nt][0], o[nt][1]);
        *(float2*)&g_acc[pb1 * H + c] = make_float2(o[nt][2], o[nt][3]);
    }
    if ((lane & 3) == 0) {
        g_m[pb0] = m0; g_l[pb0] = l0;
        g_m[pb1] = m1; g_l[pb1] = l1;
    }
}

// ---------------------------------------------------------------------------
// Kernel 3: combine split-K partials (exp2 domain).
// ---------------------------------------------------------------------------
__global__ __launch_bounds__(256) void combine_kernel(float* __restrict__ out)
{
    int idx   = blockIdx.x * 256 + threadIdx.x;
    int d     = idx & (H - 1);
    int query = idx >> 6;

    float mv[NSPLIT];
    float M = -1e30f;
#pragma unroll
    for (int i = 0; i < NSPLIT; i++) {
        mv[i] = g_m[query * NSPLIT + i];
        M = fmaxf(M, mv[i]);
    }

    float L = 0.0f, o = 0.0f;
#pragma unroll
    for (int i = 0; i < NSPLIT; i++) {
        float w = exp2f(mv[i] - M);
        L += g_l[query * NSPLIT + i] * w;
        o += g_acc[((size_t)query * NSPLIT + i) * H + d] * w;
    }
    out[idx] = o / L;
}

// ---------------------------------------------------------------------------
extern "C" void kernel_launch(void* const* d_in, const int* in_sizes, int n_in,
                              void* d_out, int out_size)
{
    const float* x  = (const float*)d_in[0];
    const float* Wq = (const float*)d_in[1];
    const float* Wk = (const float*)d_in[2];
    const float* Wv = (const float*)d_in[3];
    float* out = (float*)d_out;

    // unconditional (no static guards): host-side, idempotent, capture-safe
    cudaFuncSetAttribute(qkv_mma_kernel,
        cudaFuncAttributeMaxDynamicSharedMemorySize, 8 * TILE_BYTES);
    cudaFuncSetAttribute(flash_mma_kernel,
        cudaFuncAttributeMaxDynamicSharedMemorySize, 4 * SLOT_BYTES);

    prep_x_kernel<<<(size_t)M_TOT * C / 2048, 256>>>(x);
    prep_w_kernel<<<3 * C * H / 2048, 256>>>(Wq, Wk, Wv);
    qkv_mma_kernel<<<dim3(M_TOT / 64, 3), 128, 8 * TILE_BYTES>>>();
    flash_mma_kernel<<<dim3(T / 64, NSPLIT, BATCH), 128, 4 * SLOT_BYTES>>>();
    combine_kernel<<<(M_TOT * H) / 256, 256>>>(out);
}

// round 8
// speedup vs baseline: 1.1039x; 1.1039x over previous
#include <cuda_runtime.h>
#include <cuda_bf16.h>
#include <math.h>
#include <stdint.h>

#define BATCH 4
#define T 4096
#define C 768
#define H 64
#define M_TOT (BATCH * T)

// work-balanced split-K: fixed 512-key chunks, up to 8 per query tile
#define NCHUNK 8
#define CHUNK_KEYS 512

// scale folded with log2(e): softmax computed in exp2 domain
#define SC_LOG2 0.180336881f   // 0.125 * log2(e)

// ---- pre-converted bf16 hi/lo operand arrays ----
__device__ __align__(16) __nv_bfloat16 g_xhi[(size_t)M_TOT * C];
__device__ __align__(16) __nv_bfloat16 g_xlo[(size_t)M_TOT * C];
__device__ __align__(16) __nv_bfloat16 g_Whi[3 * C * H];
__device__ __align__(16) __nv_bfloat16 g_Wlo[3 * C * H];
__device__ __align__(16) __nv_bfloat16 g_Qhi[M_TOT * H];
__device__ __align__(16) __nv_bfloat16 g_Qlo[M_TOT * H];
__device__ __align__(16) __nv_bfloat16 g_Khi[M_TOT * H];
__device__ __align__(16) __nv_bfloat16 g_Klo[M_TOT * H];
__device__ __align__(16) __nv_bfloat16 g_Vhi[M_TOT * H];
__device__ __align__(16) __nv_bfloat16 g_Vlo[M_TOT * H];
__device__ float g_m[(size_t)M_TOT * NCHUNK];
__device__ float g_l[(size_t)M_TOT * NCHUNK];
__device__ float g_acc[(size_t)M_TOT * NCHUNK * H];

// ============================================================================
// Primitives
// ============================================================================
__device__ __forceinline__ uint32_t smem_to_u32(const void* smem_ptr) {
    uint32_t addr;
    asm("{ .reg .u64 tmp; cvta.to.shared.u64 tmp, %1; cvt.u32.u64 %0, tmp; }"
        : "=r"(addr) : "l"(smem_ptr));
    return addr;
}

__device__ __forceinline__ void mma16816(float* d, const uint32_t* a, const uint32_t* b) {
    asm volatile(
        "mma.sync.aligned.m16n8k16.row.col.f32.bf16.bf16.f32 "
        "{%0,%1,%2,%3}, {%4,%5,%6,%7}, {%8,%9}, {%0,%1,%2,%3};"
        : "+f"(d[0]), "+f"(d[1]), "+f"(d[2]), "+f"(d[3])
        : "r"(a[0]), "r"(a[1]), "r"(a[2]), "r"(a[3]), "r"(b[0]), "r"(b[1]));
}

__device__ __forceinline__ void ldsm_x4(uint32_t* r, uint32_t a) {
    asm volatile("ldmatrix.sync.aligned.m8n8.x4.shared.b16 {%0,%1,%2,%3}, [%4];"
        : "=r"(r[0]), "=r"(r[1]), "=r"(r[2]), "=r"(r[3]) : "r"(a));
}

__device__ __forceinline__ void ldsm_x4_t(uint32_t* r, uint32_t a) {
    asm volatile("ldmatrix.sync.aligned.m8n8.x4.trans.shared.b16 {%0,%1,%2,%3}, [%4];"
        : "=r"(r[0]), "=r"(r[1]), "=r"(r[2]), "=r"(r[3]) : "r"(a));
}

#define CP16(dst, src) \
    asm volatile("cp.async.cg.shared.global [%0], [%1], 16;" \
                 :: "r"(dst), "l"(src) : "memory")
#define CP_COMMIT() asm volatile("cp.async.commit_group;" ::: "memory")
#define CP_WAIT0()  asm volatile("cp.async.wait_group 0;" ::: "memory")
#define CP_WAIT1()  asm volatile("cp.async.wait_group 1;" ::: "memory")

__device__ __forceinline__ void cvt_hilo(float vx, float vy, uint32_t& hi, uint32_t& lo) {
    __nv_bfloat162 h = __floats2bfloat162_rn(vx, vy);
    hi = *reinterpret_cast<uint32_t*>(&h);
    float rx = vx - __bfloat162float(h.x);
    float ry = vy - __bfloat162float(h.y);
    __nv_bfloat162 l2 = __floats2bfloat162_rn(rx, ry);
    lo = *reinterpret_cast<uint32_t*>(&l2);
}

// SMEM tile: 64 rows x 64 bf16, 144B row stride (conflict-free ldmatrix)
#define SKB 144
#define TILE_BYTES (64 * SKB)         // 9216
#define KV_SLOT (4 * TILE_BYTES)      // Khi|Klo|Vhi|Vlo = 36864
#define FLASH_SMEM (2 * KV_SLOT)      // 73728 (2-stage)

// ---------------------------------------------------------------------------
// Prep kernels: fp32 -> bf16 hi/lo, once.
// ---------------------------------------------------------------------------
__global__ __launch_bounds__(256) void prep_x_kernel(const float* __restrict__ x)
{
    size_t i = ((size_t)blockIdx.x * 256 + threadIdx.x) * 8;
    float4 a = *(const float4*)(x + i);
    float4 b = *(const float4*)(x + i + 4);
    uint32_t h[4], l[4];
    cvt_hilo(a.x, a.y, h[0], l[0]);
    cvt_hilo(a.z, a.w, h[1], l[1]);
    cvt_hilo(b.x, b.y, h[2], l[2]);
    cvt_hilo(b.z, b.w, h[3], l[3]);
    *(uint4*)(g_xhi + i) = make_uint4(h[0], h[1], h[2], h[3]);
    *(uint4*)(g_xlo + i) = make_uint4(l[0], l[1], l[2], l[3]);
}

__global__ __launch_bounds__(256) void prep_w_kernel(
    const float* __restrict__ Wq, const float* __restrict__ Wk,
    const float* __restrict__ Wv)
{
    size_t i = ((size_t)blockIdx.x * 256 + threadIdx.x) * 8;
    int which = (int)(i / (C * H));
    const float* W = (which == 0) ? Wq : (which == 1) ? Wk : Wv;
    size_t local = i - (size_t)which * (C * H);
    float4 a = *(const float4*)(W + local);
    float4 b = *(const float4*)(W + local + 4);
    uint32_t h[4], l[4];
    cvt_hilo(a.x, a.y, h[0], l[0]);
    cvt_hilo(a.z, a.w, h[1], l[1]);
    cvt_hilo(b.x, b.y, h[2], l[2]);
    cvt_hilo(b.z, b.w, h[3], l[3]);
    *(uint4*)(g_Whi + i) = make_uint4(h[0], h[1], h[2], h[3]);
    *(uint4*)(g_Wlo + i) = make_uint4(l[0], l[1], l[2], l[3]);
}

extern __shared__ __align__(16) char dyn_sm[];

// ---------------------------------------------------------------------------
// Kernel 1: QKV projection, 2-stage pipelined (unchanged; proven).
// ---------------------------------------------------------------------------
__global__ __launch_bounds__(128, 3) void qkv_mma_kernel()
{
    const int y    = blockIdx.y;
    const int tid  = threadIdx.x;
    const int wid  = tid >> 5;
    const int lane = tid & 31;
    const int m0g  = blockIdx.x * 64;
    const uint32_t smb = smem_to_u32(dyn_sm);

    const char* srcs[4] = {
        (const char*)g_xhi, (const char*)g_xlo,
        (const char*)(g_Whi + (size_t)y * C * H),
        (const char*)(g_Wlo + (size_t)y * C * H) };

    auto stage = [&](int t) {
        uint32_t base = smb + (t & 1) * (4 * TILE_BYTES);
        int k0 = t * 64;
#pragma unroll
        for (int i = 0; i < 16; i++) {
            int id = i * 128 + tid;
            const int arr = i >> 2;
            int within = id & 511;
            int r = within >> 3, c = within & 7;
            uint32_t dst = base + arr * TILE_BYTES + r * SKB + c * 16;
            const char* src = (arr < 2)
                ? srcs[arr] + ((size_t)(m0g + r) * C + k0 + c * 8) * 2
                : srcs[arr] + ((size_t)(k0 + r) * H + c * 8) * 2;
            CP16(dst, src);
        }
        CP_COMMIT();
    };

    float o[8][4];
#pragma unroll
    for (int nt = 0; nt < 8; nt++)
#pragma unroll
        for (int e = 0; e < 4; e++) o[nt][e] = 0.0f;

    const int a_row  = wid * 16 + (lane & 7) + ((lane >> 3) & 1) * 8;
    const int a_colb = (lane >> 4) * 8;
    const int g      = lane >> 3;
    const int t_row  = (lane & 7) + (g & 1) * 8;
    const int t_colb = (g >> 1) * 8;

    const int NT = C / 64;
    stage(0);
    stage(1);

    for (int t = 0; t < NT; t++) {
        if (t + 2 <= NT) CP_WAIT1(); else CP_WAIT0();
        __syncthreads();
        uint32_t bb = smb + (t & 1) * (4 * TILE_BYTES);

        uint32_t axh[4][4], axl[4][4];
#pragma unroll
        for (int k = 0; k < 4; k++) {
            uint32_t ad = a_row * SKB + (k * 16 + a_colb) * 2;
            ldsm_x4(axh[k], bb + 0          + ad);
            ldsm_x4(axl[k], bb + TILE_BYTES + ad);
        }

#pragma unroll
        for (int np = 0; np < 4; np++) {
#pragma unroll
            for (int k = 0; k < 4; k++) {
                uint32_t bh[4], bl[4];
                uint32_t ad = (k * 16 + t_row) * SKB + (np * 16 + t_colb) * 2;
                ldsm_x4_t(bh, bb + 2 * TILE_BYTES + ad);
                ldsm_x4_t(bl, bb + 3 * TILE_BYTES + ad);
                mma16816(o[2 * np],     axh[k], bh);
                mma16816(o[2 * np + 1], axh[k], bh + 2);
                mma16816(o[2 * np],     axh[k], bl);
                mma16816(o[2 * np + 1], axh[k], bl + 2);
                mma16816(o[2 * np],     axl[k], bh);
                mma16816(o[2 * np + 1], axl[k], bh + 2);
            }
        }
        __syncthreads();
        if (t + 2 < NT) stage(t + 2);
    }

    __nv_bfloat16* ohi = (y == 0) ? g_Qhi : (y == 1) ? g_Khi : g_Vhi;
    __nv_bfloat16* olo = (y == 0) ? g_Qlo : (y == 1) ? g_Klo : g_Vlo;
    const int r0 = m0g + wid * 16 + (lane >> 2);
#pragma unroll
    for (int nt = 0; nt < 8; nt++) {
        int c = nt * 8 + (lane & 3) * 2;
        uint32_t hi, lo;
        cvt_hilo(o[nt][0], o[nt][1], hi, lo);
        *(uint32_t*)(ohi + (size_t)r0 * H + c) = hi;
        *(uint32_t*)(olo + (size_t)r0 * H + c) = lo;
        cvt_hilo(o[nt][2], o[nt][3], hi, lo);
        *(uint32_t*)(ohi + (size_t)(r0 + 8) * H + c) = hi;
        *(uint32_t*)(olo + (size_t)(r0 + 8) * H + c) = lo;
    }
}

// ---------------------------------------------------------------------------
// Kernel 2: flash attention, work-balanced 512-key chunks.
// grid = (T/64, NCHUNK, BATCH), block = 128 (4 warps x 16 queries).
// SMEM: 2 slots of [Khi|Klo|Vhi|Vlo], 2-stage cp.async pipeline.
// ---------------------------------------------------------------------------
__global__ __launch_bounds__(128, 3) void flash_mma_kernel()
{
    const int b     = blockIdx.z;
    const int chunk = blockIdx.y;
    const int qt    = blockIdx.x;
    const int tid   = threadIdx.x;
    const int wid   = tid >> 5;
    const int lane  = tid & 31;
    const int q0    = qt * 64;

    const int seg_begin = chunk * CHUNK_KEYS;
    const int seg_end   = min(seg_begin + CHUNK_KEYS, q0 + 64);

    if (seg_begin >= seg_end) {            // chunk beyond causal range
        for (int r = tid; r < 64; r += 128) {
            size_t pb = ((size_t)(b * T) + q0 + r) * NCHUNK + chunk;
            g_m[pb] = -1e30f;
            g_l[pb] = 0.0f;
        }
        return;
    }

    const uint32_t smb = smem_to_u32(dyn_sm);
    const int NT = (seg_end - seg_begin + 63) / 64;   // 1..8

    const char* kvsrc[4] = {
        (const char*)g_Khi, (const char*)g_Klo,
        (const char*)g_Vhi, (const char*)g_Vlo };

    auto stage = [&](int t) {
        uint32_t base = smb + (t & 1) * KV_SLOT;
        int kt = seg_begin + t * 64;
#pragma unroll
        for (int i = 0; i < 16; i++) {
            int id = i * 128 + tid;            // 0..2047
            const int arr = i >> 2;            // compile-time: Khi Klo Vhi Vlo
            int within = id & 511;
            int r = within >> 3, c = within & 7;
            uint32_t dst = base + arr * TILE_BYTES + r * SKB + c * 16;
            const char* src = kvsrc[arr] + ((size_t)(b * T + kt + r) * H + c * 8) * 2;
            CP16(dst, src);
        }
        CP_COMMIT();
    };

    // ---- Q fragments straight from global (canonical m16n8k16 A layout) ----
    uint32_t qh[4][4], ql[4][4];
    {
        const int rl = wid * 16 + (lane >> 2);
        const int tg = lane & 3;
        const uint32_t* Qh32 = (const uint32_t*)(g_Qhi + (size_t)(b * T + q0) * H);
        const uint32_t* Ql32 = (const uint32_t*)(g_Qlo + (size_t)(b * T + q0) * H);
#pragma unroll
        for (int k = 0; k < 4; k++) {
            int cb = k * 8 + tg;
            qh[k][0] = Qh32[(size_t)rl * 32 + cb];
            qh[k][1] = Qh32[(size_t)(rl + 8) * 32 + cb];
            qh[k][2] = Qh32[(size_t)rl * 32 + cb + 4];
            qh[k][3] = Qh32[(size_t)(rl + 8) * 32 + cb + 4];
            ql[k][0] = Ql32[(size_t)rl * 32 + cb];
            ql[k][1] = Ql32[(size_t)(rl + 8) * 32 + cb];
            ql[k][2] = Ql32[(size_t)rl * 32 + cb + 4];
            ql[k][3] = Ql32[(size_t)(rl + 8) * 32 + cb + 4];
        }
    }

    stage(0);
    if (NT > 1) stage(1);

    const int g      = lane >> 3;
    const int nt_row = (lane & 7) + (g >> 1) * 8;
    const int nt_colb = (g & 1) * 8;
    const int t_row  = (lane & 7) + (g & 1) * 8;
    const int t_colb = (g >> 1) * 8;

    float o[8][4];
#pragma unroll
    for (int nt = 0; nt < 8; nt++)
#pragma unroll
        for (int e = 0; e < 4; e++) o[nt][e] = 0.0f;
    float m0 = -1e30f, m1 = -1e30f, l0 = 0.0f, l1 = 0.0f;

    const int row_i0 = (wid << 4) + (lane >> 2);

    for (int t = 0; t < NT; t++) {
        if (t + 2 <= NT) CP_WAIT1(); else CP_WAIT0();
        __syncthreads();
        const uint32_t bb = smb + (t & 1) * KV_SLOT;
        const int kt = seg_begin + t * 64;

        // ---- S = Q K^T (3-term bf16 split) ----
        float s[8][4];
#pragma unroll
        for (int nt = 0; nt < 8; nt++)
#pragma unroll
            for (int e = 0; e < 4; e++) s[nt][e] = 0.0f;

#pragma unroll
        for (int np = 0; np < 4; np++) {
#pragma unroll
            for (int k = 0; k < 4; k++) {
                uint32_t bh[4], bl[4];
                uint32_t ad = (np * 16 + nt_row) * SKB + (k * 16 + nt_colb) * 2;
                ldsm_x4(bh, bb + ad);
                ldsm_x4(bl, bb + TILE_BYTES + ad);
                mma16816(s[2 * np],     qh[k], bh);
                mma16816(s[2 * np + 1], qh[k], bh + 2);
                mma16816(s[2 * np],     qh[k], bl);
                mma16816(s[2 * np + 1], qh[k], bl + 2);
                mma16816(s[2 * np],     ql[k], bh);
                mma16816(s[2 * np + 1], ql[k], bh + 2);
            }
        }

        // ---- online softmax (exp2 domain) ----
        const bool needmask = (kt + 63 > q0 + (wid << 4));
        float mn0 = -1e30f, mn1 = -1e30f;
#pragma unroll
        for (int nt = 0; nt < 8; nt++) {
#pragma unroll
            for (int e = 0; e < 4; e++) {
                float v = s[nt][e] * SC_LOG2;
                if (needmask) {
                    int j = kt + nt * 8 + (lane & 3) * 2 + (e & 1);
                    int i = q0 + row_i0 + (e >> 1) * 8;
                    if (j > i) v = -INFINITY;
                }
                s[nt][e] = v;
            }
            mn0 = fmaxf(mn0, fmaxf(s[nt][0], s[nt][1]));
            mn1 = fmaxf(mn1, fmaxf(s[nt][2], s[nt][3]));
        }
        mn0 = fmaxf(mn0, __shfl_xor_sync(0xFFFFFFFFu, mn0, 1));
        mn0 = fmaxf(mn0, __shfl_xor_sync(0xFFFFFFFFu, mn0, 2));
        mn1 = fmaxf(mn1, __shfl_xor_sync(0xFFFFFFFFu, mn1, 1));
        mn1 = fmaxf(mn1, __shfl_xor_sync(0xFFFFFFFFu, mn1, 2));
        mn0 = fmaxf(mn0, -1e30f);
        mn1 = fmaxf(mn1, -1e30f);

        float mnew0 = fmaxf(m0, mn0), mnew1 = fmaxf(m1, mn1);
        float a0 = exp2f(m0 - mnew0), a1 = exp2f(m1 - mnew1);
        m0 = mnew0; m1 = mnew1;

        float ls0 = 0.0f, ls1 = 0.0f;
#pragma unroll
        for (int nt = 0; nt < 8; nt++) {
            float p0 = exp2f(s[nt][0] - mnew0);
            float p1 = exp2f(s[nt][1] - mnew0);
            float p2 = exp2f(s[nt][2] - mnew1);
            float p3 = exp2f(s[nt][3] - mnew1);
            s[nt][0] = p0; s[nt][1] = p1; s[nt][2] = p2; s[nt][3] = p3;
            ls0 += p0 + p1;
            ls1 += p2 + p3;
            o[nt][0] *= a0; o[nt][1] *= a0;
            o[nt][2] *= a1; o[nt][3] *= a1;
        }
        ls0 += __shfl_xor_sync(0xFFFFFFFFu, ls0, 1);
        ls0 += __shfl_xor_sync(0xFFFFFFFFu, ls0, 2);
        ls1 += __shfl_xor_sync(0xFFFFFFFFu, ls1, 1);
        ls1 += __shfl_xor_sync(0xFFFFFFFFu, ls1, 2);
        l0 = l0 * a0 + ls0;
        l1 = l1 * a1 + ls1;

        // ---- O += P V (3-term) ----
#pragma unroll
        for (int k = 0; k < 4; k++) {
            uint32_t aPh[4], aPl[4];
#pragma unroll
            for (int h = 0; h < 2; h++) {
                int nt = 2 * k + h;
                cvt_hilo(s[nt][0], s[nt][1], aPh[h * 2 + 0], aPl[h * 2 + 0]);
                cvt_hilo(s[nt][2], s[nt][3], aPh[h * 2 + 1], aPl[h * 2 + 1]);
            }
#pragma unroll
            for (int dp = 0; dp < 4; dp++) {
                uint32_t bh[4], bl[4];
                uint32_t ad = (k * 16 + t_row) * SKB + (dp * 16 + t_colb) * 2;
                ldsm_x4_t(bh, bb + 2 * TILE_BYTES + ad);
                ldsm_x4_t(bl, bb + 3 * TILE_BYTES + ad);
                mma16816(o[2 * dp],     aPh, bh);
                mma16816(o[2 * dp + 1], aPh, bh + 2);
                mma16816(o[2 * dp],     aPh, bl);
                mma16816(o[2 * dp + 1], aPh, bl + 2);
                mma16816(o[2 * dp],     aPl, bh);
                mma16816(o[2 * dp + 1], aPl, bh + 2);
            }
        }
        __syncthreads();                    // all reads of slot done
        if (t + 2 < NT) stage(t + 2);       // safe: slot (t&1) free
    }

    // ---- write chunk partials (m in log2 domain) ----
    const int r0g = q0 + row_i0;
    const size_t pb0 = ((size_t)(b * T) + r0g) * NCHUNK + chunk;
    const size_t pb1 = ((size_t)(b * T) + r0g + 8) * NCHUNK + chunk;
#pragma unroll
    for (int nt = 0; nt < 8; nt++) {
        int c = nt * 8 + (lane & 3) * 2;
        *(float2*)&g_acc[pb0 * H + c] = make_float2(o[nt][0], o[nt][1]);
        *(float2*)&g_acc[pb1 * H + c] = make_float2(o[nt][2], o[nt][3]);
    }
    if ((lane & 3) == 0) {
        g_m[pb0] = m0; g_l[pb0] = l0;
        g_m[pb1] = m1; g_l[pb1] = l1;
    }
}

// ---------------------------------------------------------------------------
// Kernel 3: combine chunk partials (exp2 domain).
// ---------------------------------------------------------------------------
__global__ __launch_bounds__(256) void combine_kernel(float* __restrict__ out)
{
    int idx   = blockIdx.x * 256 + threadIdx.x;
    int d     = idx & (H - 1);
    int query = idx >> 6;

    float mv[NCHUNK];
    float M = -1e30f;
#pragma unroll
    for (int i = 0; i < NCHUNK; i++) {
        mv[i] = g_m[(size_t)query * NCHUNK + i];
        M = fmaxf(M, mv[i]);
    }

    float L = 0.0f, o = 0.0f;
#pragma unroll
    for (int i = 0; i < NCHUNK; i++) {
        float w = exp2f(mv[i] - M);            // empty chunk -> 0
        L += g_l[(size_t)query * NCHUNK + i] * w;
        o += g_acc[((size_t)query * NCHUNK + i) * H + d] * w;
    }
    out[idx] = o / L;
}

// ---------------------------------------------------------------------------
extern "C" void kernel_launch(void* const* d_in, const int* in_sizes, int n_in,
                              void* d_out, int out_size)
{
    const float* x  = (const float*)d_in[0];
    const float* Wq = (const float*)d_in[1];
    const float* Wk = (const float*)d_in[2];
    const float* Wv = (const float*)d_in[3];
    float* out = (float*)d_out;

    // host-side, idempotent, capture-safe
    cudaFuncSetAttribute(qkv_mma_kernel,
        cudaFuncAttributeMaxDynamicSharedMemorySize, 8 * TILE_BYTES);
    cudaFuncSetAttribute(flash_mma_kernel,
        cudaFuncAttributeMaxDynamicSharedMemorySize, FLASH_SMEM);

    prep_x_kernel<<<(size_t)M_TOT * C / 2048, 256>>>(x);
    prep_w_kernel<<<3 * C * H / 2048, 256>>>(Wq, Wk, Wv);
    qkv_mma_kernel<<<dim3(M_TOT / 64, 3), 128, 8 * TILE_BYTES>>>();
    flash_mma_kernel<<<dim3(T / 64, NCHUNK, BATCH), 128, FLASH_SMEM>>>();
    combine_kernel<<<(M_TOT * H) / 256, 256>>>(out);
}